// round 4
// baseline (speedup 1.0000x reference)
#include <cuda_runtime.h>
#include <math.h>

#define MAXN 100000
#define HDIM 64

// Scratch (allocation-free rule: __device__ globals)
__device__ __align__(256) float g_hs[(size_t)MAXN * HDIM];   // (x@W) * dinv[row]
__device__ __align__(256) float g_acc[(size_t)MAXN * HDIM];  // aggregation accumulator
__device__ __align__(256) float g_buf[(size_t)MAXN * HDIM];  // layer output / next input
__device__ float g_deg[MAXN];
__device__ float g_dinv[MAXN];

// ---------------- degree ----------------
__global__ void zero_deg_kernel(int n) {
    int i = blockIdx.x * blockDim.x + threadIdx.x;
    if (i < n) g_deg[i] = 0.0f;
}

__global__ void count_deg_kernel(const int* __restrict__ dst, int E) {
    int i = blockIdx.x * blockDim.x + threadIdx.x;
    if (i < E) atomicAdd(&g_deg[dst[i]], 1.0f);
}

__global__ void dinv_kernel(int n) {
    int i = blockIdx.x * blockDim.x + threadIdx.x;
    if (i < n) g_dinv[i] = rsqrtf(g_deg[i] + 1.0f);
}

// ---------------- GEMM: hs = (X @ W) * dinv, acc = hs (self-loop init) ----------------
// Block = 256 threads (8 warps), 64 rows per block.
// W transposed into shared (padded), X tile in shared, warp does 8 rows x 64 cols,
// lane handles cols {lane, lane+32}, float4 over k.
template <int K>
__global__ __launch_bounds__(256) void gemm_kernel(const float* __restrict__ Xin,
                                                   const float* __restrict__ W, int n) {
    constexpr int KP = K + 4;  // pad; KP%4==0 keeps float4 alignment, stride-4-bank offset -> conflict-free
    extern __shared__ float smem[];
    float* sWt = smem;            // [64][KP]  (transposed W)
    float* sX  = smem + 64 * KP;  // [64][K]

    const float* X = Xin ? Xin : g_buf;
    int tid = threadIdx.x;

    for (int i = tid; i < K * 64; i += 256) {
        int k = i >> 6, c = i & 63;
        sWt[c * KP + k] = W[i];
    }
    int row0 = blockIdx.x * 64;
    int nrows = n - row0; if (nrows > 64) nrows = 64;
    for (int i = tid; i < nrows * K; i += 256) sX[i] = X[(size_t)row0 * K + i];
    __syncthreads();

    int w = tid >> 5, lane = tid & 31;
    float a0[8], a1[8];
#pragma unroll
    for (int r = 0; r < 8; r++) { a0[r] = 0.0f; a1[r] = 0.0f; }

    const float4* wt0 = (const float4*)(sWt + lane * KP);
    const float4* wt1 = (const float4*)(sWt + (lane + 32) * KP);
#pragma unroll 4
    for (int k4 = 0; k4 < K / 4; k4++) {
        float4 w0 = wt0[k4];
        float4 w1 = wt1[k4];
#pragma unroll
        for (int r = 0; r < 8; r++) {
            float4 xv = ((const float4*)(sX + (w * 8 + r) * K))[k4];
            a0[r] += xv.x * w0.x + xv.y * w0.y + xv.z * w0.z + xv.w * w0.w;
            a1[r] += xv.x * w1.x + xv.y * w1.y + xv.z * w1.z + xv.w * w1.w;
        }
    }

#pragma unroll
    for (int r = 0; r < 8; r++) {
        int row = row0 + w * 8 + r;
        if (row < n) {
            float dv = g_dinv[row];
            float h0 = a0[r] * dv, h1 = a1[r] * dv;
            size_t o = (size_t)row * HDIM;
            g_hs[o + lane] = h0;        g_hs[o + lane + 32] = h1;
            g_acc[o + lane] = h0;       g_acc[o + lane + 32] = h1;
        }
    }
}

// ---------------- edge scatter: acc[dst] += hs[src] ----------------
// 16 threads per edge, one float4 red per thread (64 floats/row).
__global__ __launch_bounds__(256) void scatter_kernel(const int* __restrict__ src,
                                                      const int* __restrict__ dst, int E) {
    int gtid = blockIdx.x * 256 + threadIdx.x;
    int e = gtid >> 4;
    if (e >= E) return;
    int j = gtid & 15;
    int s = __ldg(src + e);
    int d = __ldg(dst + e);
    float4 v = ((const float4*)(g_hs + (size_t)s * HDIM))[j];
    float* addr = g_acc + (size_t)d * HDIM + (j << 2);
    asm volatile("red.global.add.v4.f32 [%0], {%1,%2,%3,%4};"
                 :: "l"(addr), "f"(v.x), "f"(v.y), "f"(v.z), "f"(v.w) : "memory");
}

// ---------------- post: y = LN(acc*dinv + b)*g+be -> gelu ; optional fused head ----------------
__global__ __launch_bounds__(256) void post_kernel(const float* __restrict__ b,
                                                   const float* __restrict__ g,
                                                   const float* __restrict__ be, int n, int last,
                                                   const float* __restrict__ Wh,
                                                   const float* __restrict__ bh,
                                                   float* __restrict__ out) {
    int w = threadIdx.x >> 5, lane = threadIdx.x & 31;
    int row = blockIdx.x * 8 + w;
    if (row >= n) return;
    size_t o = (size_t)row * HDIM;
    float dv = g_dinv[row];
    float v0 = g_acc[o + lane] * dv + b[lane];
    float v1 = g_acc[o + lane + 32] * dv + b[lane + 32];

    float s = v0 + v1;
#pragma unroll
    for (int off = 16; off; off >>= 1) s += __shfl_xor_sync(0xffffffffu, s, off);
    float m = s * (1.0f / 64.0f);
    float d0 = v0 - m, d1 = v1 - m;
    float vv = d0 * d0 + d1 * d1;
#pragma unroll
    for (int off = 16; off; off >>= 1) vv += __shfl_xor_sync(0xffffffffu, vv, off);
    float rs = rsqrtf(vv * (1.0f / 64.0f) + 1e-5f);

    float y0 = d0 * rs * g[lane] + be[lane];
    float y1 = d1 * rs * g[lane + 32] + be[lane + 32];
    // exact GELU (erf)
    y0 = 0.5f * y0 * (1.0f + erff(y0 * 0.70710678118654752f));
    y1 = 0.5f * y1 * (1.0f + erff(y1 * 0.70710678118654752f));

    if (!last) {
        g_buf[o + lane] = y0;
        g_buf[o + lane + 32] = y1;
    } else {
        float hsum = y0 * Wh[lane] + y1 * Wh[lane + 32];
#pragma unroll
        for (int off = 16; off; off >>= 1) hsum += __shfl_xor_sync(0xffffffffu, hsum, off);
        if (lane == 0) out[row] = hsum + bh[0];
    }
}

extern "C" void kernel_launch(void* const* d_in, const int* in_sizes, int n_in,
                              void* d_out, int out_size) {
    const float* x   = (const float*)d_in[0];
    const int*   ei  = (const int*)d_in[1];
    const float* W1  = (const float*)d_in[2];
    const float* b1  = (const float*)d_in[3];
    const float* g1  = (const float*)d_in[4];
    const float* be1 = (const float*)d_in[5];
    const float* W2  = (const float*)d_in[6];
    const float* b2  = (const float*)d_in[7];
    const float* g2  = (const float*)d_in[8];
    const float* be2 = (const float*)d_in[9];
    const float* W3  = (const float*)d_in[10];
    const float* b3  = (const float*)d_in[11];
    const float* g3  = (const float*)d_in[12];
    const float* be3 = (const float*)d_in[13];
    const float* Wh  = (const float*)d_in[14];
    const float* bh  = (const float*)d_in[15];
    float* out = (float*)d_out;

    int N = in_sizes[0] / 128;
    int E = in_sizes[1] / 2;
    const int* src = ei;
    const int* dst = ei + E;

    size_t sh128 = (size_t)64 * (132 + 128) * sizeof(float);  // 66560 B
    size_t sh64  = (size_t)64 * (68 + 64) * sizeof(float);    // 33792 B
    cudaFuncSetAttribute(gemm_kernel<128>, cudaFuncAttributeMaxDynamicSharedMemorySize, (int)sh128);
    cudaFuncSetAttribute(gemm_kernel<64>,  cudaFuncAttributeMaxDynamicSharedMemorySize, (int)sh64);

    int gblocks = (N + 63) / 64;
    int sblocks = (int)(((long long)E * 16 + 255) / 256);
    int pblocks = (N + 7) / 8;

    zero_deg_kernel<<<(N + 255) / 256, 256>>>(N);
    count_deg_kernel<<<(E + 255) / 256, 256>>>(dst, E);
    dinv_kernel<<<(N + 255) / 256, 256>>>(N);

    // layer 1 (K=128)
    gemm_kernel<128><<<gblocks, 256, sh128>>>(x, W1, N);
    scatter_kernel<<<sblocks, 256>>>(src, dst, E);
    post_kernel<<<pblocks, 256>>>(b1, g1, be1, N, 0, nullptr, nullptr, nullptr);

    // layer 2 (K=64)
    gemm_kernel<64><<<gblocks, 256, sh64>>>(nullptr, W2, N);
    scatter_kernel<<<sblocks, 256>>>(src, dst, E);
    post_kernel<<<pblocks, 256>>>(b2, g2, be2, N, 0, nullptr, nullptr, nullptr);

    // layer 3 (K=64) + fused head
    gemm_kernel<64><<<gblocks, 256, sh64>>>(nullptr, W3, N);
    scatter_kernel<<<sblocks, 256>>>(src, dst, E);
    post_kernel<<<pblocks, 256>>>(b3, g3, be3, N, 1, Wh, bh, out);
}

// round 6
// speedup vs baseline: 1.4765x; 1.4765x over previous
#include <cuda_runtime.h>
#include <math.h>

#define MAXN 100000
#define MAXE 1600000
#define HDIM 64
#define SCAN_B 1024

// Scratch (__device__ globals; no allocation allowed)
__device__ __align__(256) float g_hs[(size_t)MAXN * HDIM];   // (x@W) * dinv[row]
__device__ __align__(256) float g_buf[(size_t)MAXN * HDIM];  // layer output / next input
__device__ float g_dinv[MAXN];
__device__ int g_cnt[MAXN];        // in-degree histogram
__device__ int g_rowptr[MAXN + 1]; // CSR row offsets (by dst)
__device__ int g_cursor[MAXN];     // fill cursors
__device__ int g_csrc[MAXE];       // CSR src indices
__device__ int g_bsum[(MAXN + SCAN_B - 1) / SCAN_B];

// ---------------- CSR build ----------------
__global__ void zero_cnt_kernel(int n) {
    int i = blockIdx.x * blockDim.x + threadIdx.x;
    if (i < n) g_cnt[i] = 0;
}

__global__ void hist_kernel(const int* __restrict__ dst, int E) {
    int i = blockIdx.x * blockDim.x + threadIdx.x;
    if (i < E) atomicAdd(&g_cnt[dst[i]], 1);
}

// block-local exclusive scan of counts; block totals to g_bsum
__global__ __launch_bounds__(SCAN_B) void scan1_kernel(int n) {
    __shared__ int wsum[32];
    int i = blockIdx.x * SCAN_B + threadIdx.x;
    int lane = threadIdx.x & 31, w = threadIdx.x >> 5;
    int v = (i < n) ? g_cnt[i] : 0;
    int x = v;
#pragma unroll
    for (int off = 1; off < 32; off <<= 1) {
        int t = __shfl_up_sync(0xffffffffu, x, off);
        if (lane >= off) x += t;
    }
    if (lane == 31) wsum[w] = x;
    __syncthreads();
    if (w == 0) {
        int s = wsum[lane];
#pragma unroll
        for (int off = 1; off < 32; off <<= 1) {
            int t = __shfl_up_sync(0xffffffffu, s, off);
            if (lane >= off) s += t;
        }
        wsum[lane] = s;
    }
    __syncthreads();
    int incl = x + (w > 0 ? wsum[w - 1] : 0);
    if (i < n) g_rowptr[i] = incl - v;
    if (threadIdx.x == SCAN_B - 1) g_bsum[blockIdx.x] = incl;
}

__global__ void scan2_kernel(int nb) {
    if (threadIdx.x == 0) {
        int run = 0;
        for (int i = 0; i < nb; i++) { int t = g_bsum[i]; g_bsum[i] = run; run += t; }
    }
}

// add block offsets; init cursors; compute dinv; set rowptr[n]
__global__ __launch_bounds__(SCAN_B) void scan3_kernel(int n, int E) {
    int i = blockIdx.x * SCAN_B + threadIdx.x;
    if (i < n) {
        int r = g_rowptr[i] + g_bsum[blockIdx.x];
        g_rowptr[i] = r;
        g_cursor[i] = r;
        g_dinv[i] = rsqrtf((float)g_cnt[i] + 1.0f);
    }
    if (i == 0) g_rowptr[n] = E;
}

__global__ void fill_kernel(const int* __restrict__ src, const int* __restrict__ dst, int E) {
    int i = blockIdx.x * blockDim.x + threadIdx.x;
    if (i < E) {
        int pos = atomicAdd(&g_cursor[dst[i]], 1);
        g_csrc[pos] = src[i];
    }
}

// ---------------- GEMM: hs = (X @ W) * dinv ----------------
template <int K>
__global__ __launch_bounds__(256) void gemm_kernel(const float* __restrict__ Xin,
                                                   const float* __restrict__ W, int n) {
    constexpr int KP = K + 4;
    extern __shared__ float smem[];
    float* sWt = smem;            // [64][KP] transposed W
    float* sX  = smem + 64 * KP;  // [64][K]

    const float* X = Xin ? Xin : g_buf;
    int tid = threadIdx.x;

    for (int i = tid; i < K * 64; i += 256) {
        int k = i >> 6, c = i & 63;
        sWt[c * KP + k] = W[i];
    }
    int row0 = blockIdx.x * 64;
    int nrows = n - row0; if (nrows > 64) nrows = 64;
    for (int i = tid; i < nrows * K; i += 256) sX[i] = X[(size_t)row0 * K + i];
    __syncthreads();

    int w = tid >> 5, lane = tid & 31;
    float a0[8], a1[8];
#pragma unroll
    for (int r = 0; r < 8; r++) { a0[r] = 0.0f; a1[r] = 0.0f; }

    const float4* wt0 = (const float4*)(sWt + lane * KP);
    const float4* wt1 = (const float4*)(sWt + (lane + 32) * KP);
#pragma unroll 4
    for (int k4 = 0; k4 < K / 4; k4++) {
        float4 w0 = wt0[k4];
        float4 w1 = wt1[k4];
#pragma unroll
        for (int r = 0; r < 8; r++) {
            float4 xv = ((const float4*)(sX + (w * 8 + r) * K))[k4];
            a0[r] += xv.x * w0.x + xv.y * w0.y + xv.z * w0.z + xv.w * w0.w;
            a1[r] += xv.x * w1.x + xv.y * w1.y + xv.z * w1.z + xv.w * w1.w;
        }
    }

#pragma unroll
    for (int r = 0; r < 8; r++) {
        int row = row0 + w * 8 + r;
        if (row < n) {
            float dv = g_dinv[row];
            size_t o = (size_t)row * HDIM;
            g_hs[o + lane]      = a0[r] * dv;
            g_hs[o + lane + 32] = a1[r] * dv;
        }
    }
}

// ---------------- fused aggregate + LN + GELU (+ head) ----------------
// warp per node, lane covers cols {lane, lane+32}
__global__ __launch_bounds__(256) void agg_post_kernel(const float* __restrict__ b,
                                                       const float* __restrict__ g,
                                                       const float* __restrict__ be, int n, int last,
                                                       const float* __restrict__ Wh,
                                                       const float* __restrict__ bh,
                                                       float* __restrict__ out) {
    int w = threadIdx.x >> 5, lane = threadIdx.x & 31;
    int row = blockIdx.x * 8 + w;
    if (row >= n) return;

    size_t o = (size_t)row * HDIM;
    float a0 = g_hs[o + lane];        // self-loop term (hs already scaled)
    float a1 = g_hs[o + lane + 32];

    int beg = g_rowptr[row], end = g_rowptr[row + 1];
    for (int base = beg; base < end; base += 32) {
        int e = base + lane;
        int s = (e < end) ? g_csrc[e] : 0;
        int cnt = end - base; if (cnt > 32) cnt = 32;
        for (int j = 0; j < cnt; j++) {
            int sj = __shfl_sync(0xffffffffu, s, j);
            size_t so = (size_t)sj * HDIM;
            a0 += __ldg(g_hs + so + lane);
            a1 += __ldg(g_hs + so + lane + 32);
        }
    }

    float dv = g_dinv[row];
    float v0 = a0 * dv + b[lane];
    float v1 = a1 * dv + b[lane + 32];

    float s = v0 + v1;
#pragma unroll
    for (int off = 16; off; off >>= 1) s += __shfl_xor_sync(0xffffffffu, s, off);
    float m = s * (1.0f / 64.0f);
    float d0 = v0 - m, d1 = v1 - m;
    float vv = d0 * d0 + d1 * d1;
#pragma unroll
    for (int off = 16; off; off >>= 1) vv += __shfl_xor_sync(0xffffffffu, vv, off);
    float rs = rsqrtf(vv * (1.0f / 64.0f) + 1e-5f);

    float y0 = d0 * rs * g[lane] + be[lane];
    float y1 = d1 * rs * g[lane + 32] + be[lane + 32];
    y0 = 0.5f * y0 * (1.0f + erff(y0 * 0.70710678118654752f));
    y1 = 0.5f * y1 * (1.0f + erff(y1 * 0.70710678118654752f));

    if (!last) {
        g_buf[o + lane] = y0;
        g_buf[o + lane + 32] = y1;
    } else {
        float hsum = y0 * Wh[lane] + y1 * Wh[lane + 32];
#pragma unroll
        for (int off = 16; off; off >>= 1) hsum += __shfl_xor_sync(0xffffffffu, hsum, off);
        if (lane == 0) out[row] = hsum + bh[0];
    }
}

extern "C" void kernel_launch(void* const* d_in, const int* in_sizes, int n_in,
                              void* d_out, int out_size) {
    const float* x   = (const float*)d_in[0];
    const int*   ei  = (const int*)d_in[1];
    const float* W1  = (const float*)d_in[2];
    const float* b1  = (const float*)d_in[3];
    const float* g1  = (const float*)d_in[4];
    const float* be1 = (const float*)d_in[5];
    const float* W2  = (const float*)d_in[6];
    const float* b2  = (const float*)d_in[7];
    const float* g2  = (const float*)d_in[8];
    const float* be2 = (const float*)d_in[9];
    const float* W3  = (const float*)d_in[10];
    const float* b3  = (const float*)d_in[11];
    const float* g3  = (const float*)d_in[12];
    const float* be3 = (const float*)d_in[13];
    const float* Wh  = (const float*)d_in[14];
    const float* bh  = (const float*)d_in[15];
    float* out = (float*)d_out;

    int N = in_sizes[0] / 128;
    int E = in_sizes[1] / 2;
    const int* src = ei;
    const int* dst = ei + E;

    size_t sh128 = (size_t)64 * (132 + 128) * sizeof(float);
    size_t sh64  = (size_t)64 * (68 + 64) * sizeof(float);
    cudaFuncSetAttribute(gemm_kernel<128>, cudaFuncAttributeMaxDynamicSharedMemorySize, (int)sh128);
    cudaFuncSetAttribute(gemm_kernel<64>,  cudaFuncAttributeMaxDynamicSharedMemorySize, (int)sh64);

    int nscan = (N + SCAN_B - 1) / SCAN_B;
    int gblocks = (N + 63) / 64;
    int ablocks = (N + 7) / 8;

    // CSR build (once, reused by all 3 layers) + dinv
    zero_cnt_kernel<<<(N + 255) / 256, 256>>>(N);
    hist_kernel<<<(E + 255) / 256, 256>>>(dst, E);
    scan1_kernel<<<nscan, SCAN_B>>>(N);
    scan2_kernel<<<1, 32>>>(nscan);
    scan3_kernel<<<nscan, SCAN_B>>>(N, E);
    fill_kernel<<<(E + 255) / 256, 256>>>(src, dst, E);

    // layer 1 (K=128)
    gemm_kernel<128><<<gblocks, 256, sh128>>>(x, W1, N);
    agg_post_kernel<<<ablocks, 256>>>(b1, g1, be1, N, 0, nullptr, nullptr, nullptr);

    // layer 2 (K=64)
    gemm_kernel<64><<<gblocks, 256, sh64>>>(nullptr, W2, N);
    agg_post_kernel<<<ablocks, 256>>>(b2, g2, be2, N, 0, nullptr, nullptr, nullptr);

    // layer 3 (K=64) + fused head
    gemm_kernel<64><<<gblocks, 256, sh64>>>(nullptr, W3, N);
    agg_post_kernel<<<ablocks, 256>>>(b3, g3, be3, N, 1, Wh, bh, out);
}

// round 7
// speedup vs baseline: 1.5500x; 1.0497x over previous
#include <cuda_runtime.h>
#include <math.h>

#define MAXN 100000
#define MAXE 1600000
#define HDIM 64
#define SCAN_B 1024

// Scratch (__device__ globals; no allocation allowed)
__device__ __align__(256) float g_hs[(size_t)MAXN * HDIM];   // (x@W) * dinv[row]
__device__ __align__(256) float g_buf[(size_t)MAXN * HDIM];  // layer output / next input
__device__ float g_dinv[MAXN];
__device__ int g_cnt[MAXN];        // in-degree histogram
__device__ int g_rowptr[MAXN + 1]; // CSR row offsets (by dst)
__device__ int g_cursor[MAXN];     // fill cursors
__device__ int g_csrc[MAXE];       // CSR src indices
__device__ int g_bsum[(MAXN + SCAN_B - 1) / SCAN_B];

// packed f32x2 FMA: d = a*b + c on two fp32 lanes in one instruction (B300)
#define FMA2(d, a, b, c) \
    asm("fma.rn.f32x2 %0, %1, %2, %3;" : "=l"(d) : "l"(a), "l"(b), "l"(c))

// ---------------- CSR build ----------------
__global__ void zero_cnt_kernel(int n) {
    int i = blockIdx.x * blockDim.x + threadIdx.x;
    if (i < n) g_cnt[i] = 0;
}

__global__ void hist_kernel(const int* __restrict__ dst, int E) {
    int i = blockIdx.x * blockDim.x + threadIdx.x;
    if (i < E) atomicAdd(&g_cnt[dst[i]], 1);
}

// block-local exclusive scan of counts; block totals to g_bsum
__global__ __launch_bounds__(SCAN_B) void scan1_kernel(int n) {
    __shared__ int wsum[32];
    int i = blockIdx.x * SCAN_B + threadIdx.x;
    int lane = threadIdx.x & 31, w = threadIdx.x >> 5;
    int v = (i < n) ? g_cnt[i] : 0;
    int x = v;
#pragma unroll
    for (int off = 1; off < 32; off <<= 1) {
        int t = __shfl_up_sync(0xffffffffu, x, off);
        if (lane >= off) x += t;
    }
    if (lane == 31) wsum[w] = x;
    __syncthreads();
    if (w == 0) {
        int s = wsum[lane];
#pragma unroll
        for (int off = 1; off < 32; off <<= 1) {
            int t = __shfl_up_sync(0xffffffffu, s, off);
            if (lane >= off) s += t;
        }
        wsum[lane] = s;
    }
    __syncthreads();
    int incl = x + (w > 0 ? wsum[w - 1] : 0);
    if (i < n) g_rowptr[i] = incl - v;
    if (threadIdx.x == SCAN_B - 1) g_bsum[blockIdx.x] = incl;
}

// parallel exclusive scan of block sums (nb <= 128), one block of 128 threads
__global__ __launch_bounds__(128) void scan2_kernel(int nb) {
    __shared__ int ws[4];
    int tid = threadIdx.x, lane = tid & 31, w = tid >> 5;
    int v = (tid < nb) ? g_bsum[tid] : 0;
    int x = v;
#pragma unroll
    for (int off = 1; off < 32; off <<= 1) {
        int t = __shfl_up_sync(0xffffffffu, x, off);
        if (lane >= off) x += t;
    }
    if (lane == 31) ws[w] = x;
    __syncthreads();
    int add = 0;
#pragma unroll
    for (int j = 0; j < 4; j++) add += (j < w) ? ws[j] : 0;
    if (tid < nb) g_bsum[tid] = x + add - v;  // exclusive
}

// add block offsets; init cursors; compute dinv; set rowptr[n]
__global__ __launch_bounds__(SCAN_B) void scan3_kernel(int n, int E) {
    int i = blockIdx.x * SCAN_B + threadIdx.x;
    if (i < n) {
        int r = g_rowptr[i] + g_bsum[blockIdx.x];
        g_rowptr[i] = r;
        g_cursor[i] = r;
        g_dinv[i] = rsqrtf((float)g_cnt[i] + 1.0f);
    }
    if (i == 0) g_rowptr[n] = E;
}

__global__ void fill_kernel(const int* __restrict__ src, const int* __restrict__ dst, int E) {
    int i = blockIdx.x * blockDim.x + threadIdx.x;
    if (i < E) {
        int pos = atomicAdd(&g_cursor[dst[i]], 1);
        g_csrc[pos] = src[i];
    }
}

// ---------------- GEMM: hs = (X @ W) * dinv (packed f32x2 FMA) ----------------
// Block = 256 threads (8 warps), 64 rows per block. Accumulate even/odd k
// partial sums in the two f32x2 lanes; both operands come pre-paired from
// contiguous smem float4 loads (no packing instructions needed).
template <int K>
__global__ __launch_bounds__(256) void gemm_kernel(const float* __restrict__ Xin,
                                                   const float* __restrict__ W, int n) {
    constexpr int KP = K + 4;
    extern __shared__ float smem[];
    float* sWt = smem;            // [64][KP] transposed W
    float* sX  = smem + 64 * KP;  // [64][K]

    const float* X = Xin ? Xin : g_buf;
    int tid = threadIdx.x;

    for (int i = tid; i < K * 64; i += 256) {
        int k = i >> 6, c = i & 63;
        sWt[c * KP + k] = W[i];
    }
    int row0 = blockIdx.x * 64;
    int nrows = n - row0; if (nrows > 64) nrows = 64;
    for (int i = tid; i < nrows * K; i += 256) sX[i] = X[(size_t)row0 * K + i];
    __syncthreads();

    int w = tid >> 5, lane = tid & 31;
    unsigned long long acc0[8], acc1[8];  // (even-k sum, odd-k sum) pairs
#pragma unroll
    for (int r = 0; r < 8; r++) { acc0[r] = 0ull; acc1[r] = 0ull; }

    const ulonglong2* wt0 = (const ulonglong2*)(sWt + lane * KP);
    const ulonglong2* wt1 = (const ulonglong2*)(sWt + (lane + 32) * KP);
#pragma unroll 4
    for (int k4 = 0; k4 < K / 4; k4++) {
        ulonglong2 w0 = wt0[k4];   // cols lane: k pairs (2k4, 2k4+1)
        ulonglong2 w1 = wt1[k4];   // cols lane+32
#pragma unroll
        for (int r = 0; r < 8; r++) {
            ulonglong2 xv = ((const ulonglong2*)(sX + (w * 8 + r) * K))[k4];
            FMA2(acc0[r], w0.x, xv.x, acc0[r]);
            FMA2(acc0[r], w0.y, xv.y, acc0[r]);
            FMA2(acc1[r], w1.x, xv.x, acc1[r]);
            FMA2(acc1[r], w1.y, xv.y, acc1[r]);
        }
    }

#pragma unroll
    for (int r = 0; r < 8; r++) {
        int row = row0 + w * 8 + r;
        if (row < n) {
            float dv = g_dinv[row];
            float e0, o0, e1, o1;
            asm("mov.b64 {%0, %1}, %2;" : "=f"(e0), "=f"(o0) : "l"(acc0[r]));
            asm("mov.b64 {%0, %1}, %2;" : "=f"(e1), "=f"(o1) : "l"(acc1[r]));
            size_t o = (size_t)row * HDIM;
            g_hs[o + lane]      = (e0 + o0) * dv;
            g_hs[o + lane + 32] = (e1 + o1) * dv;
        }
    }
}

// ---------------- fused aggregate + LN + GELU (+ head) ----------------
// warp per node, lane covers cols {lane, lane+32}
__global__ __launch_bounds__(256) void agg_post_kernel(const float* __restrict__ b,
                                                       const float* __restrict__ g,
                                                       const float* __restrict__ be, int n, int last,
                                                       const float* __restrict__ Wh,
                                                       const float* __restrict__ bh,
                                                       float* __restrict__ out) {
    int w = threadIdx.x >> 5, lane = threadIdx.x & 31;
    int row = blockIdx.x * 8 + w;
    if (row >= n) return;

    size_t o = (size_t)row * HDIM;
    float a0 = g_hs[o + lane];        // self-loop term (hs already scaled)
    float a1 = g_hs[o + lane + 32];

    int beg = g_rowptr[row], end = g_rowptr[row + 1];
    for (int base = beg; base < end; base += 32) {
        int e = base + lane;
        int s = (e < end) ? g_csrc[e] : 0;
        int cnt = end - base; if (cnt > 32) cnt = 32;
        for (int j = 0; j < cnt; j++) {
            int sj = __shfl_sync(0xffffffffu, s, j);
            size_t so = (size_t)sj * HDIM;
            a0 += __ldg(g_hs + so + lane);
            a1 += __ldg(g_hs + so + lane + 32);
        }
    }

    float dv = g_dinv[row];
    float v0 = a0 * dv + b[lane];
    float v1 = a1 * dv + b[lane + 32];

    float s = v0 + v1;
#pragma unroll
    for (int off = 16; off; off >>= 1) s += __shfl_xor_sync(0xffffffffu, s, off);
    float m = s * (1.0f / 64.0f);
    float d0 = v0 - m, d1 = v1 - m;
    float vv = d0 * d0 + d1 * d1;
#pragma unroll
    for (int off = 16; off; off >>= 1) vv += __shfl_xor_sync(0xffffffffu, vv, off);
    float rs = rsqrtf(vv * (1.0f / 64.0f) + 1e-5f);

    float y0 = d0 * rs * g[lane] + be[lane];
    float y1 = d1 * rs * g[lane + 32] + be[lane + 32];
    y0 = 0.5f * y0 * (1.0f + erff(y0 * 0.70710678118654752f));
    y1 = 0.5f * y1 * (1.0f + erff(y1 * 0.70710678118654752f));

    if (!last) {
        g_buf[o + lane] = y0;
        g_buf[o + lane + 32] = y1;
    } else {
        float hsum = y0 * Wh[lane] + y1 * Wh[lane + 32];
#pragma unroll
        for (int off = 16; off; off >>= 1) hsum += __shfl_xor_sync(0xffffffffu, hsum, off);
        if (lane == 0) out[row] = hsum + bh[0];
    }
}

extern "C" void kernel_launch(void* const* d_in, const int* in_sizes, int n_in,
                              void* d_out, int out_size) {
    const float* x   = (const float*)d_in[0];
    const int*   ei  = (const int*)d_in[1];
    const float* W1  = (const float*)d_in[2];
    const float* b1  = (const float*)d_in[3];
    const float* g1  = (const float*)d_in[4];
    const float* be1 = (const float*)d_in[5];
    const float* W2  = (const float*)d_in[6];
    const float* b2  = (const float*)d_in[7];
    const float* g2  = (const float*)d_in[8];
    const float* be2 = (const float*)d_in[9];
    const float* W3  = (const float*)d_in[10];
    const float* b3  = (const float*)d_in[11];
    const float* g3  = (const float*)d_in[12];
    const float* be3 = (const float*)d_in[13];
    const float* Wh  = (const float*)d_in[14];
    const float* bh  = (const float*)d_in[15];
    float* out = (float*)d_out;

    int N = in_sizes[0] / 128;
    int E = in_sizes[1] / 2;
    const int* src = ei;
    const int* dst = ei + E;

    size_t sh128 = (size_t)64 * (132 + 128) * sizeof(float);
    size_t sh64  = (size_t)64 * (68 + 64) * sizeof(float);
    cudaFuncSetAttribute(gemm_kernel<128>, cudaFuncAttributeMaxDynamicSharedMemorySize, (int)sh128);
    cudaFuncSetAttribute(gemm_kernel<64>,  cudaFuncAttributeMaxDynamicSharedMemorySize, (int)sh64);

    int nscan = (N + SCAN_B - 1) / SCAN_B;
    int gblocks = (N + 63) / 64;
    int ablocks = (N + 7) / 8;

    // CSR build (once, reused by all 3 layers) + dinv
    zero_cnt_kernel<<<(N + 255) / 256, 256>>>(N);
    hist_kernel<<<(E + 255) / 256, 256>>>(dst, E);
    scan1_kernel<<<nscan, SCAN_B>>>(N);
    scan2_kernel<<<1, 128>>>(nscan);
    scan3_kernel<<<nscan, SCAN_B>>>(N, E);
    fill_kernel<<<(E + 255) / 256, 256>>>(src, dst, E);

    // layer 1 (K=128)
    gemm_kernel<128><<<gblocks, 256, sh128>>>(x, W1, N);
    agg_post_kernel<<<ablocks, 256>>>(b1, g1, be1, N, 0, nullptr, nullptr, nullptr);

    // layer 2 (K=64)
    gemm_kernel<64><<<gblocks, 256, sh64>>>(nullptr, W2, N);
    agg_post_kernel<<<ablocks, 256>>>(b2, g2, be2, N, 0, nullptr, nullptr, nullptr);

    // layer 3 (K=64) + fused head
    gemm_kernel<64><<<gblocks, 256, sh64>>>(nullptr, W3, N);
    agg_post_kernel<<<ablocks, 256>>>(b3, g3, be3, N, 1, Wh, bh, out);
}

// round 8
// speedup vs baseline: 1.6075x; 1.0371x over previous
#include <cuda_runtime.h>
#include <math.h>

#define MAXN 100000
#define MAXE 1600000
#define HDIM 64
#define SCAN_B 1024

// Scratch (__device__ globals; no allocation allowed)
__device__ __align__(256) float g_hs[(size_t)MAXN * HDIM];   // (x@W) * dinv[row]
__device__ __align__(256) float g_buf[(size_t)MAXN * HDIM];  // layer output / next input
__device__ float g_dinv[MAXN];
__device__ int g_cnt[MAXN];        // in-degree histogram
__device__ int g_rowptr[MAXN + 1]; // CSR row offsets (by dst)
__device__ int g_cursor[MAXN];     // fill cursors
__device__ int g_csrc[MAXE];       // CSR src indices
__device__ int g_btotal[128];      // per-block totals (+1 sentinel) for decoupled scan

// packed f32x2 ops (B300)
#define FMA2(d, a, b, c) \
    asm("fma.rn.f32x2 %0, %1, %2, %3;" : "=l"(d) : "l"(a), "l"(b), "l"(c))
#define ADD2(d, a, b) \
    asm("add.rn.f32x2 %0, %1, %2;" : "=l"(d) : "l"(a), "l"(b))

// ---------------- CSR build ----------------
__global__ void zero_cnt_kernel(int n) {
    int i = blockIdx.x * blockDim.x + threadIdx.x;
    if (i < n) g_cnt[i] = 0;
    if (i < 128) g_btotal[i] = 0;
}

__global__ void hist_kernel(const int* __restrict__ dst, int E) {
    int i = blockIdx.x * blockDim.x + threadIdx.x;
    if (i < E) atomicAdd(&g_cnt[dst[i]], 1);
}

// Single-launch scan over g_cnt: block-local scan + decoupled lookback.
// Grid must be <= 128 blocks and fully wave-1 resident (98 blocks on 148 SMs).
__global__ __launch_bounds__(SCAN_B) void scan_fused_kernel(int n, int E) {
    __shared__ int wsum[32];
    __shared__ int s_prefix;
    int bid = blockIdx.x;
    int i = bid * SCAN_B + threadIdx.x;
    int lane = threadIdx.x & 31, w = threadIdx.x >> 5;
    int v = (i < n) ? g_cnt[i] : 0;
    int x = v;
#pragma unroll
    for (int off = 1; off < 32; off <<= 1) {
        int t = __shfl_up_sync(0xffffffffu, x, off);
        if (lane >= off) x += t;
    }
    if (lane == 31) wsum[w] = x;
    __syncthreads();
    if (w == 0) {
        int s = wsum[lane];
#pragma unroll
        for (int off = 1; off < 32; off <<= 1) {
            int t = __shfl_up_sync(0xffffffffu, s, off);
            if (lane >= off) s += t;
        }
        wsum[lane] = s;
    }
    __syncthreads();
    int incl = x + (w > 0 ? wsum[w - 1] : 0);

    // publish own total ASAP, then parallel lookback over predecessors
    if (threadIdx.x == 0) {
        s_prefix = 0;
        atomicExch(&g_btotal[bid], wsum[31] + 1);  // sentinel +1 (0 == not ready)
    }
    __syncthreads();
    if (threadIdx.x < bid) {
        int t;
        do { t = atomicAdd(&g_btotal[threadIdx.x], 0); } while (t == 0);
        atomicAdd_block(&s_prefix, t - 1);
    }
    __syncthreads();
    int prefix = s_prefix;

    if (i < n) {
        int r = prefix + incl - v;
        g_rowptr[i] = r;
        g_cursor[i] = r;
        g_dinv[i] = rsqrtf((float)v + 1.0f);
    }
    if (i == 0) g_rowptr[n] = E;
}

__global__ void fill_kernel(const int* __restrict__ src, const int* __restrict__ dst, int E) {
    int i = blockIdx.x * blockDim.x + threadIdx.x;
    if (i < E) {
        int pos = atomicAdd(&g_cursor[dst[i]], 1);
        g_csrc[pos] = src[i];
    }
}

// ---------------- GEMM: hs = (X @ W) * dinv (packed f32x2 FMA) ----------------
template <int K>
__global__ __launch_bounds__(256) void gemm_kernel(const float* __restrict__ Xin,
                                                   const float* __restrict__ W, int n) {
    constexpr int KP = K + 4;
    extern __shared__ float smem[];
    float* sWt = smem;            // [64][KP] transposed W
    float* sX  = smem + 64 * KP;  // [64][K]

    const float* X = Xin ? Xin : g_buf;
    int tid = threadIdx.x;

    for (int i = tid; i < K * 64; i += 256) {
        int k = i >> 6, c = i & 63;
        sWt[c * KP + k] = W[i];
    }
    int row0 = blockIdx.x * 64;
    int nrows = n - row0; if (nrows > 64) nrows = 64;
    for (int i = tid; i < nrows * K; i += 256) sX[i] = X[(size_t)row0 * K + i];
    __syncthreads();

    int w = tid >> 5, lane = tid & 31;
    unsigned long long acc0[8], acc1[8];  // (even-k sum, odd-k sum) pairs
#pragma unroll
    for (int r = 0; r < 8; r++) { acc0[r] = 0ull; acc1[r] = 0ull; }

    const ulonglong2* wt0 = (const ulonglong2*)(sWt + lane * KP);
    const ulonglong2* wt1 = (const ulonglong2*)(sWt + (lane + 32) * KP);
#pragma unroll 4
    for (int k4 = 0; k4 < K / 4; k4++) {
        ulonglong2 w0 = wt0[k4];
        ulonglong2 w1 = wt1[k4];
#pragma unroll
        for (int r = 0; r < 8; r++) {
            ulonglong2 xv = ((const ulonglong2*)(sX + (w * 8 + r) * K))[k4];
            FMA2(acc0[r], w0.x, xv.x, acc0[r]);
            FMA2(acc0[r], w0.y, xv.y, acc0[r]);
            FMA2(acc1[r], w1.x, xv.x, acc1[r]);
            FMA2(acc1[r], w1.y, xv.y, acc1[r]);
        }
    }

#pragma unroll
    for (int r = 0; r < 8; r++) {
        int row = row0 + w * 8 + r;
        if (row < n) {
            float dv = g_dinv[row];
            float e0, o0, e1, o1;
            asm("mov.b64 {%0, %1}, %2;" : "=f"(e0), "=f"(o0) : "l"(acc0[r]));
            asm("mov.b64 {%0, %1}, %2;" : "=f"(e1), "=f"(o1) : "l"(acc1[r]));
            size_t o = (size_t)row * HDIM;
            g_hs[o + lane]      = (e0 + o0) * dv;
            g_hs[o + lane + 32] = (e1 + o1) * dv;
        }
    }
}

// ---------------- fused aggregate + LN + GELU (+ head) ----------------
// warp per node; lane covers cols {2*lane, 2*lane+1} via LDG.64 + packed adds
__global__ __launch_bounds__(256) void agg_post_kernel(const float* __restrict__ b,
                                                       const float* __restrict__ g,
                                                       const float* __restrict__ be, int n, int last,
                                                       const float* __restrict__ Wh,
                                                       const float* __restrict__ bh,
                                                       float* __restrict__ out) {
    int w = threadIdx.x >> 5, lane = threadIdx.x & 31;
    int row = blockIdx.x * 8 + w;
    if (row >= n) return;

    const unsigned long long* hs2 = (const unsigned long long*)g_hs;
    size_t ro = (size_t)row * 32 + lane;
    unsigned long long aE = hs2[ro];  // self-loop term (hs already dinv-scaled)
    unsigned long long aO = 0ull;     // packed (0.0f, 0.0f)

    int beg = g_rowptr[row], end = g_rowptr[row + 1];
    for (int base = beg; base < end; base += 32) {
        int e = base + lane;
        int s = (e < end) ? g_csrc[e] : 0;
        int cnt = end - base; if (cnt > 32) cnt = 32;
        int j = 0;
        for (; j + 2 <= cnt; j += 2) {
            int s0 = __shfl_sync(0xffffffffu, s, j);
            int s1 = __shfl_sync(0xffffffffu, s, j + 1);
            unsigned long long v0 = __ldg(hs2 + (size_t)s0 * 32 + lane);
            unsigned long long v1 = __ldg(hs2 + (size_t)s1 * 32 + lane);
            ADD2(aE, aE, v0);
            ADD2(aO, aO, v1);
        }
        if (j < cnt) {
            int s0 = __shfl_sync(0xffffffffu, s, j);
            unsigned long long v0 = __ldg(hs2 + (size_t)s0 * 32 + lane);
            ADD2(aE, aE, v0);
        }
    }

    unsigned long long at;
    ADD2(at, aE, aO);
    float a0, a1;
    asm("mov.b64 {%0, %1}, %2;" : "=f"(a0), "=f"(a1) : "l"(at));

    float dv = g_dinv[row];
    float2 bb = ((const float2*)b)[lane];
    float v0 = a0 * dv + bb.x;
    float v1 = a1 * dv + bb.y;

    float s = v0 + v1;
#pragma unroll
    for (int off = 16; off; off >>= 1) s += __shfl_xor_sync(0xffffffffu, s, off);
    float m = s * (1.0f / 64.0f);
    float d0 = v0 - m, d1 = v1 - m;
    float vv = d0 * d0 + d1 * d1;
#pragma unroll
    for (int off = 16; off; off >>= 1) vv += __shfl_xor_sync(0xffffffffu, vv, off);
    float rs = rsqrtf(vv * (1.0f / 64.0f) + 1e-5f);

    float2 gg = ((const float2*)g)[lane];
    float2 ee = ((const float2*)be)[lane];
    float y0 = d0 * rs * gg.x + ee.x;
    float y1 = d1 * rs * gg.y + ee.y;
    y0 = 0.5f * y0 * (1.0f + erff(y0 * 0.70710678118654752f));
    y1 = 0.5f * y1 * (1.0f + erff(y1 * 0.70710678118654752f));

    if (!last) {
        float2 yy; yy.x = y0; yy.y = y1;
        ((float2*)g_buf)[ro] = yy;
    } else {
        float2 wh = ((const float2*)Wh)[lane];
        float hsum = y0 * wh.x + y1 * wh.y;
#pragma unroll
        for (int off = 16; off; off >>= 1) hsum += __shfl_xor_sync(0xffffffffu, hsum, off);
        if (lane == 0) out[row] = hsum + bh[0];
    }
}

extern "C" void kernel_launch(void* const* d_in, const int* in_sizes, int n_in,
                              void* d_out, int out_size) {
    const float* x   = (const float*)d_in[0];
    const int*   ei  = (const int*)d_in[1];
    const float* W1  = (const float*)d_in[2];
    const float* b1  = (const float*)d_in[3];
    const float* g1  = (const float*)d_in[4];
    const float* be1 = (const float*)d_in[5];
    const float* W2  = (const float*)d_in[6];
    const float* b2  = (const float*)d_in[7];
    const float* g2  = (const float*)d_in[8];
    const float* be2 = (const float*)d_in[9];
    const float* W3  = (const float*)d_in[10];
    const float* b3  = (const float*)d_in[11];
    const float* g3  = (const float*)d_in[12];
    const float* be3 = (const float*)d_in[13];
    const float* Wh  = (const float*)d_in[14];
    const float* bh  = (const float*)d_in[15];
    float* out = (float*)d_out;

    int N = in_sizes[0] / 128;
    int E = in_sizes[1] / 2;
    const int* src = ei;
    const int* dst = ei + E;

    size_t sh128 = (size_t)64 * (132 + 128) * sizeof(float);
    size_t sh64  = (size_t)64 * (68 + 64) * sizeof(float);
    cudaFuncSetAttribute(gemm_kernel<128>, cudaFuncAttributeMaxDynamicSharedMemorySize, (int)sh128);
    cudaFuncSetAttribute(gemm_kernel<64>,  cudaFuncAttributeMaxDynamicSharedMemorySize, (int)sh64);

    int nscan = (N + SCAN_B - 1) / SCAN_B;  // 98 <= 128, fully wave-1 resident
    int gblocks = (N + 63) / 64;
    int ablocks = (N + 7) / 8;

    // CSR build (once, reused by all 3 layers) + dinv
    zero_cnt_kernel<<<(N + 255) / 256, 256>>>(N);
    hist_kernel<<<(E + 255) / 256, 256>>>(dst, E);
    scan_fused_kernel<<<nscan, SCAN_B>>>(N, E);
    fill_kernel<<<(E + 255) / 256, 256>>>(src, dst, E);

    // layer 1 (K=128)
    gemm_kernel<128><<<gblocks, 256, sh128>>>(x, W1, N);
    agg_post_kernel<<<ablocks, 256>>>(b1, g1, be1, N, 0, nullptr, nullptr, nullptr);

    // layer 2 (K=64)
    gemm_kernel<64><<<gblocks, 256, sh64>>>(nullptr, W2, N);
    agg_post_kernel<<<ablocks, 256>>>(b2, g2, be2, N, 0, nullptr, nullptr, nullptr);

    // layer 3 (K=64) + fused head
    gemm_kernel<64><<<gblocks, 256, sh64>>>(nullptr, W3, N);
    agg_post_kernel<<<ablocks, 256>>>(b3, g3, be3, N, 1, Wh, bh, out);
}